// round 10
// baseline (speedup 1.0000x reference)
#include <cuda_runtime.h>
#include <cstdint>

#define NCTA  128
#define NTHR  256
#define T_STEPS 512
#define BATCH 128
#define APAD  68      // staged A row: 64 floats + 4 pad; 16B-aligned, conflict-free LDS.128

// ---- global scratch (static: no allocation allowed) ----
__device__ float g_xT[T_STEPS * BATCH * 512];     // [t][b][k] time-major input
__device__ float g_spk0[2][BATCH * 1024];         // parity-double-buffered spike planes
__device__ float g_spk1[2][BATCH * 1024];
__device__ int          g_count;
__device__ volatile int g_gen;

struct __align__(16) Smem {
    float w0[8 * 512];            // [jl][k]  this CTA's 8 cols of W0
    float w1[8 * 1024];           // [jl][k]  8 cols of W1
    float w2[4 * 1024];           // [jl][k]  4 cols of W2
    float a[2][BATCH * APAD];     // double-buffered A chunks [b][64k]
    float mem0[BATCH * 8], spk0[BATCH * 8];
    float mem1[BATCH * 8], spk1[BATCH * 8];
    float mem2[BATCH * 4], spk2[BATCH * 4];
};

// ---- packed dual-fp32 FMA (SASS FFMA2): 2 exact IEEE fp32 FMAs per instr ----
__device__ __forceinline__ void fma2(unsigned long long& d,
                                     unsigned long long a, unsigned long long b) {
    asm("fma.rn.f32x2 %0, %1, %2, %0;" : "+l"(d) : "l"(a), "l"(b));
}

// ---- cp.async helpers ----
__device__ __forceinline__ void cp_async16(void* sdst, const void* gsrc) {
    uint32_t s = (uint32_t)__cvta_generic_to_shared(sdst);
    asm volatile("cp.async.cg.shared.global [%0], [%1], 16;" :: "r"(s), "l"(gsrc) : "memory");
}
__device__ __forceinline__ void cp_commit() {
    asm volatile("cp.async.commit_group;" ::: "memory");
}
__device__ __forceinline__ void cp_wait1() {
    asm volatile("cp.async.wait_group 1;" ::: "memory");
}

// Stage one 64k x 128row A chunk (32 KB) into smem. 8 x 16B per thread.
__device__ __forceinline__ void stage_chunk(float* dst, const float* src, int stride) {
    const int tid = threadIdx.x;
#pragma unroll
    for (int i = 0; i < 8; ++i) {
        int flat = tid + i * NTHR;           // 0..2047 float4 slots
        int br = flat >> 4, k4 = flat & 15;
        cp_async16(dst + br * APAD + k4 * 4, src + (size_t)br * stride + k4 * 4);
    }
}

// ---- grid barrier: 128 CTAs, 1/SM, co-resident by construction ----
__device__ __forceinline__ void grid_sync()
{
    __threadfence();
    __syncthreads();
    if (threadIdx.x == 0) {
        int gen = g_gen;
        if (atomicAdd(&g_count, 1) == NCTA - 1) {
            g_count = 0;
            __threadfence();
            g_gen = gen + 1;
        } else {
            while (g_gen == gen) { }
        }
    }
    __syncthreads();
    __threadfence();
}

// One layer tile for this CTA's column slice.
// 256 threads = (h = col half, b = batch row). C = Ctot/2 cols per thread.
// A rows streamed via double-buffered cp.async; W resident in smem.
// Inner product via FFMA2: even/odd k lanes accumulated in a packed pair.
template<int Ctot, int K, bool SkipPro>
__device__ __forceinline__ void layer_phase(
    Smem* __restrict__ sm,
    const float* __restrict__ Aglob, int Astride,
    const float* __restrict__ Ws,
    float* __restrict__ memS, float* __restrict__ spkS,
    float* __restrict__ spkOut, int outStride, int jbase)
{
    const int tid = threadIdx.x;
    const int b   = tid & 127;
    const int h   = tid >> 7;
    constexpr int C  = Ctot / 2;
    constexpr int NC = K / 64;

    if (!SkipPro) { stage_chunk(sm->a[0], Aglob, Astride); cp_commit(); }

    unsigned long long acc2[C];
#pragma unroll
    for (int j = 0; j < C; ++j) acc2[j] = 0ull;

    const ulonglong2* __restrict__ Wj[C];
#pragma unroll
    for (int j = 0; j < C; ++j)
        Wj[j] = (const ulonglong2*)(Ws + (size_t)(h * C + j) * K);

    for (int c = 0; c < NC; ++c) {
        if (c + 1 < NC) stage_chunk(sm->a[(c + 1) & 1], Aglob + (c + 1) * 64, Astride);
        cp_commit();
        cp_wait1();                      // chunk c landed; c+1 in flight
        __syncthreads();

        const ulonglong2* __restrict__ A2 =
            (const ulonglong2*)sm->a[c & 1] + (size_t)b * (APAD / 4);
        const int wbase = c * 16;
#pragma unroll
        for (int k8 = 0; k8 < 8; ++k8) {
            ulonglong2 a0 = A2[2 * k8];          // k .. k+3  (2 f32x2 lanes)
            ulonglong2 a1 = A2[2 * k8 + 1];      // k+4 .. k+7
#pragma unroll
            for (int j = 0; j < C; ++j) {
                ulonglong2 w0 = Wj[j][wbase + 2 * k8];
                ulonglong2 w1 = Wj[j][wbase + 2 * k8 + 1];
                fma2(acc2[j], a0.x, w0.x);
                fma2(acc2[j], a0.y, w0.y);
                fma2(acc2[j], a1.x, w1.x);
                fma2(acc2[j], a1.y, w1.y);
            }
        }
        __syncthreads();                 // all readers done before buffer reuse
    }

    // LIF update: mem*0.5*(1-s) exact (factor in {0,0.5}); one rounded add.
#pragma unroll
    for (int j = 0; j < C; ++j) {
        float lo  = __uint_as_float((unsigned)acc2[j]);
        float hi  = __uint_as_float((unsigned)(acc2[j] >> 32));
        float dot = lo + hi;
        int   idx = b * Ctot + h * C + j;
        float m   = memS[idx];
        float s   = spkS[idx];
        float nm  = m * (0.5f * (1.0f - s)) + dot;
        memS[idx] = nm;
        spkS[idx] = (nm > 0.3f) ? 1.0f : 0.0f;
    }

    // Cooperative coalesced spike publish (float4 per 4 cols).
    if (spkOut) {
        __syncthreads();
        constexpr int F4 = Ctot / 4;     // 2 or 1
        for (int i = tid; i < BATCH * F4; i += NTHR) {
            int bb = i / F4, q = i % F4;
            *(float4*)(spkOut + (size_t)bb * outStride + jbase + q * 4) =
                *(const float4*)(spkS + bb * Ctot + q * 4);
        }
    }
}

__global__ __launch_bounds__(NTHR, 1)
void snn_kernel(const float* __restrict__ x,
                const float* __restrict__ w0,
                const float* __restrict__ w1,
                const float* __restrict__ w2,
                float* __restrict__ out)
{
    extern __shared__ char smem_raw[];
    Smem* sm = (Smem*)smem_raw;
    const int cta = blockIdx.x;
    const int tid = threadIdx.x;

    // ---- load this CTA's weight column slices (one-time) ----
    for (int i = tid; i < 8 * 512; i += NTHR) {
        int k = i >> 3, jl = i & 7;
        sm->w0[jl * 512 + k] = w0[k * 1024 + cta * 8 + jl];
    }
    for (int i = tid; i < 8 * 1024; i += NTHR) {
        int k = i >> 3, jl = i & 7;
        sm->w1[jl * 1024 + k] = w1[k * 1024 + cta * 8 + jl];
    }
    for (int i = tid; i < 4 * 1024; i += NTHR) {
        int k = i >> 2, jl = i & 3;
        sm->w2[jl * 1024 + k] = w2[k * 512 + cta * 4 + jl];
    }
    // ---- zero private LIF state ----
    for (int i = tid; i < BATCH * 8; i += NTHR) {
        sm->mem0[i] = 0.f; sm->spk0[i] = 0.f;
        sm->mem1[i] = 0.f; sm->spk1[i] = 0.f;
    }
    for (int i = tid; i < BATCH * 4; i += NTHR) {
        sm->mem2[i] = 0.f; sm->spk2[i] = 0.f;
    }

    // ---- transpose x[b][k][t] -> g_xT[t][b][k] (32x32 smem tiles) ----
    {
        float* tile = sm->a[0];
        const int r = tid >> 5, c = tid & 31;
        for (int tl = cta; tl < BATCH * 256; tl += NCTA) {   // uniform per-CTA count
            int b   = tl >> 8;
            int rem = tl & 255;
            int k0  = (rem >> 4) << 5;
            int t0  = (rem & 15) << 5;
            const float* src = x + (size_t)b * (512 * 512);
            __syncthreads();
            for (int rr = r; rr < 32; rr += 8)
                tile[rr * 33 + c] = src[(k0 + rr) * 512 + (t0 + c)];
            __syncthreads();
            for (int rr = r; rr < 32; rr += 8)
                g_xT[(size_t)(t0 + rr) * (BATCH * 512) + b * 512 + (k0 + c)] = tile[c * 33 + rr];
        }
    }
    grid_sync();

    // Prefetch L0(0)'s first chunk (x is dependency-free).
    stage_chunk(sm->a[0], g_xT, 512);
    cp_commit();

    // ---- pipelined time loop: phase p = L0(p) || L1(p-1) || L2(p-2), 1 sync/phase ----
    for (int p = 0; p <= T_STEPS + 1; ++p) {
        if (p) grid_sync();              // publishes phase p-1 spikes

        if (p < T_STEPS)
            layer_phase<8, 512, true>(sm, g_xT + (size_t)p * (BATCH * 512), 512,
                                      sm->w0, sm->mem0, sm->spk0,
                                      g_spk0[p & 1], 1024, cta * 8);
        if (p >= 1 && p <= T_STEPS)
            layer_phase<8, 1024, false>(sm, g_spk0[(p - 1) & 1], 1024,
                                        sm->w1, sm->mem1, sm->spk1,
                                        g_spk1[(p - 1) & 1], 1024, cta * 8);
        if (p >= 2)
            layer_phase<4, 1024, false>(sm, g_spk1[(p - 2) & 1], 1024,
                                        sm->w2, sm->mem2, sm->spk2,
                                        (p == T_STEPS + 1) ? out : (float*)0,
                                        512, cta * 4);

        // Prefetch next phase's L0 chunk 0 before the barrier (x is dep-free;
        // buffer 0 is idle after the last layer's trailing __syncthreads).
        if (p + 1 < T_STEPS) {
            stage_chunk(sm->a[0], g_xT + (size_t)(p + 1) * (BATCH * 512), 512);
            cp_commit();
        }
    }
}

extern "C" void kernel_launch(void* const* d_in, const int* in_sizes, int n_in,
                              void* d_out, int out_size)
{
    const float* x  = (const float*)d_in[0];
    const float* w0 = (const float*)d_in[1];
    const float* w1 = (const float*)d_in[2];
    const float* w2 = (const float*)d_in[3];
    (void)in_sizes; (void)n_in; (void)out_size;

    int smemBytes = (int)sizeof(Smem);   // ~152 KB, needs opt-in
    cudaFuncSetAttribute(snn_kernel, cudaFuncAttributeMaxDynamicSharedMemorySize, smemBytes);
    snn_kernel<<<NCTA, NTHR, smemBytes>>>(x, w0, w1, w2, (float*)d_out);
}